// round 1
// baseline (speedup 1.0000x reference)
#include <cuda_runtime.h>
#include <math.h>

#define BATCH 4
#define SEQ   2048
#define EMB   2048
#define H_Q   16
#define H_KV  4
#define DHEAD 128
#define KVDIM (H_KV*DHEAD)     // 512
#define GQA   (H_Q/H_KV)       // 4

// ---------------- scratch (no allocations allowed) ----------------
__device__ float g_q[BATCH*SEQ*EMB];     // [B,S,H,D]
__device__ float g_k[BATCH*SEQ*KVDIM];   // [B,S,KV,D]
__device__ float g_v[BATCH*SEQ*KVDIM];   // [B,S,KV,D]
__device__ float g_o[BATCH*SEQ*EMB];     // [B,S,H,D]
__device__ float g_cos[SEQ*64];
__device__ float g_sin[SEQ*64];

// ---------------- RoPE table ----------------
__global__ void rope_table_kernel(float* ctab, float* stab) {
    int idx = blockIdx.x * blockDim.x + threadIdx.x;
    if (idx >= SEQ * 64) return;
    int pos = idx >> 6;
    int j   = idx & 63;
    // inv_freq = 10000^(-(2j)/128)
    float invf = expf(-(float)j * (9.210340371976184f / 64.0f));
    float arg = (float)pos * invf;
    float s, c;
    sincosf(arg, &s, &c);
    ctab[idx] = c;
    stab[idx] = s;
}

// ---------------- in-place RoPE on [B,S,nheads,128] ----------------
__global__ void rope_apply_kernel(float* __restrict__ t, const float* __restrict__ ctab,
                                  const float* __restrict__ stab, int nheads) {
    int idx = blockIdx.x * blockDim.x + threadIdx.x;
    int total = BATCH * SEQ * nheads * 64;
    if (idx >= total) return;
    int j  = idx & 63;
    int tt = idx >> 6;
    int h  = tt % nheads;
    int t2 = tt / nheads;
    int s  = t2 % SEQ;
    int b  = t2 / SEQ;
    float c  = ctab[s * 64 + j];
    float sn = stab[s * 64 + j];
    size_t base = (((size_t)b * SEQ + s) * nheads + h) * DHEAD;
    float x0 = t[base + j];
    float x1 = t[base + 64 + j];
    t[base + j]      = x0 * c - x1 * sn;
    t[base + 64 + j] = x1 * c + x0 * sn;
}

// ---------------- GEMM: C[M,N] = A[M,K] @ B[N,K]^T + bias[N] ----------------
// BM=128, BN=128, BK=16, 256 threads, 8x8 per thread
#define GBM 128
#define GBN 128
#define GBK 16

__global__ __launch_bounds__(256)
void gemm_nt_bias(const float* __restrict__ A, const float* __restrict__ B,
                  const float* __restrict__ bias, float* __restrict__ C,
                  int M, int N, int K) {
    __shared__ float As[GBK][GBM];
    __shared__ float Bs[GBK][GBN];

    const int bm  = blockIdx.y * GBM;
    const int bn  = blockIdx.x * GBN;
    const int tid = threadIdx.x;
    const int tr  = tid >> 4;   // 0..15 -> rows tr*8
    const int tc  = tid & 15;   // 0..15 -> cols tc*8

    float acc[8][8];
#pragma unroll
    for (int i = 0; i < 8; i++)
#pragma unroll
        for (int j = 0; j < 8; j++) acc[i][j] = 0.f;

    for (int kt = 0; kt < K; kt += GBK) {
        // load A tile (128x16) transposed into As[k][m]
#pragma unroll
        for (int it = 0; it < 2; it++) {
            int idx = tid + it * 256;          // 0..511
            int row = idx >> 2;
            int k4  = (idx & 3) * 4;
            float4 v = *(const float4*)&A[(size_t)(bm + row) * K + kt + k4];
            As[k4 + 0][row] = v.x;
            As[k4 + 1][row] = v.y;
            As[k4 + 2][row] = v.z;
            As[k4 + 3][row] = v.w;
        }
        // load B tile (128x16) transposed into Bs[k][n]
#pragma unroll
        for (int it = 0; it < 2; it++) {
            int idx = tid + it * 256;
            int row = idx >> 2;
            int k4  = (idx & 3) * 4;
            float4 v = *(const float4*)&B[(size_t)(bn + row) * K + kt + k4];
            Bs[k4 + 0][row] = v.x;
            Bs[k4 + 1][row] = v.y;
            Bs[k4 + 2][row] = v.z;
            Bs[k4 + 3][row] = v.w;
        }
        __syncthreads();

#pragma unroll
        for (int kk = 0; kk < GBK; kk++) {
            float ar[8], br[8];
            *(float4*)&ar[0] = *(const float4*)&As[kk][tr * 8];
            *(float4*)&ar[4] = *(const float4*)&As[kk][tr * 8 + 4];
            *(float4*)&br[0] = *(const float4*)&Bs[kk][tc * 8];
            *(float4*)&br[4] = *(const float4*)&Bs[kk][tc * 8 + 4];
#pragma unroll
            for (int i = 0; i < 8; i++)
#pragma unroll
                for (int j = 0; j < 8; j++) acc[i][j] += ar[i] * br[j];
        }
        __syncthreads();
    }

    float bv[8];
    *(float4*)&bv[0] = *(const float4*)&bias[bn + tc * 8];
    *(float4*)&bv[4] = *(const float4*)&bias[bn + tc * 8 + 4];

#pragma unroll
    for (int i = 0; i < 8; i++) {
        float* cp = &C[(size_t)(bm + tr * 8 + i) * N + bn + tc * 8];
        float4 r0, r1;
        r0.x = acc[i][0] + bv[0]; r0.y = acc[i][1] + bv[1];
        r0.z = acc[i][2] + bv[2]; r0.w = acc[i][3] + bv[3];
        r1.x = acc[i][4] + bv[4]; r1.y = acc[i][5] + bv[5];
        r1.z = acc[i][6] + bv[6]; r1.w = acc[i][7] + bv[7];
        *(float4*)&cp[0] = r0;
        *(float4*)&cp[4] = r1;
    }
}

// ---------------- flash attention (fp32, causal, GQA) ----------------
// q-tile = 64 rows, k-tile = 64 cols, D=128, 256 threads
// smem layout (floats): Qs_t[128][64] | Ks_t[128][64] | Vs[64][128] | Ss[64][65]
//                       m[64] | l[64] | resc[64] | pmax[4][64] | psum[4][64]
#define FL_SMEM_FLOATS (128*64 + 128*64 + 64*128 + 64*65 + 64 + 64 + 64 + 4*64 + 4*64)
#define FL_SMEM_BYTES  (FL_SMEM_FLOATS * 4)

__global__ __launch_bounds__(256)
void flash_attn_kernel(const float* __restrict__ Q, const float* __restrict__ K,
                       const float* __restrict__ V, float* __restrict__ O) {
    extern __shared__ float sm[];
    float* Qs   = sm;                 // [128][64] transposed
    float* Ks   = Qs + 128 * 64;      // [128][64] transposed
    float* Vs   = Ks + 128 * 64;      // [64][128]
    float* Ss   = Vs + 64 * 128;      // [64][65]
    float* mrow = Ss + 64 * 65;       // [64]
    float* lrow = mrow + 64;          // [64]
    float* resc = lrow + 64;          // [64]
    float* pmax = resc + 64;          // [4][64]
    float* psum = pmax + 4 * 64;      // [4][64]

    const int qt  = blockIdx.x;       // q tile 0..31
    const int bh  = blockIdx.y;       // 0..63
    const int b   = bh >> 4;
    const int h   = bh & 15;
    const int kvh = h / GQA;
    const int q0  = qt * 64;
    const int tid = threadIdx.x;
    const float scale = 0.08838834764831845f;   // 1/sqrt(128)

    // load Q tile, scaled, transposed: Qs[d][r]
#pragma unroll
    for (int it = 0; it < 8; it++) {
        int idx = tid + it * 256;       // 0..2047
        int r   = idx >> 5;
        int d4  = (idx & 31) * 4;
        float4 v = *(const float4*)&Q[(((size_t)b * SEQ + q0 + r) * H_Q + h) * DHEAD + d4];
        Qs[(d4 + 0) * 64 + r] = v.x * scale;
        Qs[(d4 + 1) * 64 + r] = v.y * scale;
        Qs[(d4 + 2) * 64 + r] = v.z * scale;
        Qs[(d4 + 3) * 64 + r] = v.w * scale;
    }
    if (tid < 64) { mrow[tid] = -1e30f; lrow[tid] = 0.f; }

    float o[4][8];
#pragma unroll
    for (int i = 0; i < 4; i++)
#pragma unroll
        for (int j = 0; j < 8; j++) o[i][j] = 0.f;

    __syncthreads();

    for (int kt = 0; kt <= qt; kt++) {
        const int k0 = kt * 64;
        // load K (transposed) and V tiles
#pragma unroll
        for (int it = 0; it < 8; it++) {
            int idx = tid + it * 256;
            int c   = idx >> 5;
            int d4  = (idx & 31) * 4;
            size_t gbase = (((size_t)b * SEQ + k0 + c) * H_KV + kvh) * DHEAD + d4;
            float4 kv = *(const float4*)&K[gbase];
            Ks[(d4 + 0) * 64 + c] = kv.x;
            Ks[(d4 + 1) * 64 + c] = kv.y;
            Ks[(d4 + 2) * 64 + c] = kv.z;
            Ks[(d4 + 3) * 64 + c] = kv.w;
            float4 vv = *(const float4*)&V[gbase];
            *(float4*)&Vs[c * 128 + d4] = vv;
        }
        __syncthreads();

        // scores: 4x4 per thread
        {
            const int tr = tid >> 4;   // rows tr*4
            const int tc = tid & 15;   // cols tc*4
            float s4[4][4];
#pragma unroll
            for (int i = 0; i < 4; i++)
#pragma unroll
                for (int j = 0; j < 4; j++) s4[i][j] = 0.f;

            for (int d = 0; d < 128; d++) {
                float4 qv = *(const float4*)&Qs[d * 64 + tr * 4];
                float4 kv = *(const float4*)&Ks[d * 64 + tc * 4];
                float qa[4] = {qv.x, qv.y, qv.z, qv.w};
                float ka[4] = {kv.x, kv.y, kv.z, kv.w};
#pragma unroll
                for (int i = 0; i < 4; i++)
#pragma unroll
                    for (int j = 0; j < 4; j++) s4[i][j] += qa[i] * ka[j];
            }
            if (kt == qt) {
#pragma unroll
                for (int i = 0; i < 4; i++)
#pragma unroll
                    for (int j = 0; j < 4; j++)
                        if (k0 + tc * 4 + j > q0 + tr * 4 + i) s4[i][j] = -1e30f;
            }
#pragma unroll
            for (int i = 0; i < 4; i++)
#pragma unroll
                for (int j = 0; j < 4; j++)
                    Ss[(tr * 4 + i) * 65 + tc * 4 + j] = s4[i][j];
        }
        __syncthreads();

        // softmax: partial max (4 segments of 16 cols per row)
        {
            int r = tid & 63, seg = tid >> 6;
            float lm = -1e30f;
#pragma unroll
            for (int c = 0; c < 16; c++) lm = fmaxf(lm, Ss[r * 65 + seg * 16 + c]);
            pmax[seg * 64 + r] = lm;
        }
        __syncthreads();
        if (tid < 64) {
            int r = tid;
            float mo = mrow[r];
            float mn = fmaxf(fmaxf(pmax[r], pmax[64 + r]), fmaxf(pmax[128 + r], pmax[192 + r]));
            mn = fmaxf(mo, mn);
            resc[r] = __expf(mo - mn);
            mrow[r] = mn;
        }
        __syncthreads();
        {
            int r = tid & 63, seg = tid >> 6;
            float mn = mrow[r];
            float sum = 0.f;
#pragma unroll
            for (int c = 0; c < 16; c++) {
                float p = __expf(Ss[r * 65 + seg * 16 + c] - mn);
                Ss[r * 65 + seg * 16 + c] = p;
                sum += p;
            }
            psum[seg * 64 + r] = sum;
        }
        __syncthreads();
        if (tid < 64) {
            int r = tid;
            lrow[r] = lrow[r] * resc[r] + psum[r] + psum[64 + r] + psum[128 + r] + psum[192 + r];
        }

        // PV: rows rg*4.., cols cg*8..
        {
            const int rg = tid >> 4;
            const int cg = tid & 15;
            float rs[4];
#pragma unroll
            for (int i = 0; i < 4; i++) rs[i] = resc[rg * 4 + i];
#pragma unroll
            for (int i = 0; i < 4; i++)
#pragma unroll
                for (int j = 0; j < 8; j++) o[i][j] *= rs[i];

            for (int kk = 0; kk < 64; kk++) {
                float pr[4];
#pragma unroll
                for (int i = 0; i < 4; i++) pr[i] = Ss[(rg * 4 + i) * 65 + kk];
                float4 v0 = *(const float4*)&Vs[kk * 128 + cg * 8];
                float4 v1 = *(const float4*)&Vs[kk * 128 + cg * 8 + 4];
                float va[8] = {v0.x, v0.y, v0.z, v0.w, v1.x, v1.y, v1.z, v1.w};
#pragma unroll
                for (int i = 0; i < 4; i++)
#pragma unroll
                    for (int j = 0; j < 8; j++) o[i][j] += pr[i] * va[j];
            }
        }
        __syncthreads();
    }

    // epilogue: normalize + store [B,S,H,D]
    {
        const int rg = tid >> 4;
        const int cg = tid & 15;
#pragma unroll
        for (int i = 0; i < 4; i++) {
            float inv = 1.f / lrow[rg * 4 + i];
            float* op = &O[(((size_t)b * SEQ + q0 + rg * 4 + i) * H_Q + h) * DHEAD + cg * 8];
            float4 w0, w1;
            w0.x = o[i][0] * inv; w0.y = o[i][1] * inv;
            w0.z = o[i][2] * inv; w0.w = o[i][3] * inv;
            w1.x = o[i][4] * inv; w1.y = o[i][5] * inv;
            w1.z = o[i][6] * inv; w1.w = o[i][7] * inv;
            *(float4*)&op[0] = w0;
            *(float4*)&op[4] = w1;
        }
    }
}

// ---------------- launch ----------------
extern "C" void kernel_launch(void* const* d_in, const int* in_sizes, int n_in,
                              void* d_out, int out_size) {
    const float* x  = (const float*)d_in[0];
    const float* wq = (const float*)d_in[1];
    const float* bq = (const float*)d_in[2];
    const float* wk = (const float*)d_in[3];
    const float* bk = (const float*)d_in[4];
    const float* wv = (const float*)d_in[5];
    const float* bv = (const float*)d_in[6];
    const float* wo = (const float*)d_in[7];
    const float* bo = (const float*)d_in[8];
    float* out = (float*)d_out;

    float *q, *k, *v, *o, *ctab, *stab;
    cudaGetSymbolAddress((void**)&q, g_q);
    cudaGetSymbolAddress((void**)&k, g_k);
    cudaGetSymbolAddress((void**)&v, g_v);
    cudaGetSymbolAddress((void**)&o, g_o);
    cudaGetSymbolAddress((void**)&ctab, g_cos);
    cudaGetSymbolAddress((void**)&stab, g_sin);

    const int M = BATCH * SEQ;   // 8192

    // RoPE tables
    rope_table_kernel<<<(SEQ * 64 + 255) / 256, 256>>>(ctab, stab);

    // QKV projections
    gemm_nt_bias<<<dim3(EMB / GBN, M / GBM), 256>>>(x, wq, bq, q, M, EMB, EMB);
    gemm_nt_bias<<<dim3(KVDIM / GBN, M / GBM), 256>>>(x, wk, bk, k, M, KVDIM, EMB);
    gemm_nt_bias<<<dim3(KVDIM / GBN, M / GBM), 256>>>(x, wv, bv, v, M, KVDIM, EMB);

    // RoPE on q and k (in place)
    {
        int tq = BATCH * SEQ * H_Q * 64;
        rope_apply_kernel<<<(tq + 255) / 256, 256>>>(q, ctab, stab, H_Q);
        int tk = BATCH * SEQ * H_KV * 64;
        rope_apply_kernel<<<(tk + 255) / 256, 256>>>(k, ctab, stab, H_KV);
    }

    // flash attention
    cudaFuncSetAttribute(flash_attn_kernel, cudaFuncAttributeMaxDynamicSharedMemorySize,
                         FL_SMEM_BYTES);
    flash_attn_kernel<<<dim3(SEQ / 64, BATCH * H_Q), 256, FL_SMEM_BYTES>>>(q, k, v, o);

    // output projection
    gemm_nt_bias<<<dim3(EMB / GBN, M / GBM), 256>>>(o, wo, bo, out, M, EMB, EMB);
}

// round 4
// speedup vs baseline: 1.4620x; 1.4620x over previous
#include <cuda_runtime.h>
#include <cuda_bf16.h>
#include <math.h>
#include <stdint.h>

#define BATCH 4
#define SEQ   2048
#define EMB   2048
#define H_Q   16
#define H_KV  4
#define DHEAD 128
#define KVDIM (H_KV*DHEAD)     // 512
#define GQA   (H_Q/H_KV)       // 4

// ---------------- scratch (no allocations allowed) ----------------
__device__ float g_q[BATCH*SEQ*EMB];     // [B,S,H,D]
__device__ float g_k[BATCH*SEQ*KVDIM];   // [B,S,KV,D]
__device__ float g_v[BATCH*SEQ*KVDIM];   // [B,S,KV,D]
__device__ float g_o[BATCH*SEQ*EMB];     // [B,S,H,D]
__device__ float g_cos[SEQ*64];
__device__ float g_sin[SEQ*64];

// bf16 hi/lo split buffers
#define XN   (BATCH*SEQ*EMB)       // 16M
#define WQN  (EMB*EMB)             // 4M
#define WKN  (KVDIM*EMB)           // 1M
__device__ __nv_bfloat16 g_xhi[XN],  g_xlo[XN];
__device__ __nv_bfloat16 g_wqhi[WQN], g_wqlo[WQN];
__device__ __nv_bfloat16 g_wkhi[WKN], g_wklo[WKN];
__device__ __nv_bfloat16 g_wvhi[WKN], g_wvlo[WKN];
__device__ __nv_bfloat16 g_wohi[WQN], g_wolo[WQN];
__device__ __nv_bfloat16 g_ohi[XN],  g_olo[XN];

// ---------------- helpers ----------------
__device__ __forceinline__ uint32_t smem_u32(const void* p) {
    uint32_t a;
    asm("{ .reg .u64 t; cvta.to.shared.u64 t, %1; cvt.u32.u64 %0, t; }" : "=r"(a) : "l"(p));
    return a;
}

__device__ __forceinline__ void cp16(uint32_t dst, const void* src) {
    asm volatile("cp.async.cg.shared.global [%0], [%1], 16;" :: "r"(dst), "l"(src) : "memory");
}
#define CP_COMMIT() asm volatile("cp.async.commit_group;" ::: "memory")
#define CP_WAIT0()  asm volatile("cp.async.wait_group 0;" ::: "memory")

__device__ __forceinline__ void ldm_x4(uint32_t* r, uint32_t addr) {
    asm volatile("ldmatrix.sync.aligned.m8n8.x4.shared.b16 {%0,%1,%2,%3}, [%4];"
                 : "=r"(r[0]), "=r"(r[1]), "=r"(r[2]), "=r"(r[3]) : "r"(addr));
}

__device__ __forceinline__ void mma16816(float* c, const uint32_t* a, uint32_t b0, uint32_t b1) {
    asm volatile(
        "mma.sync.aligned.m16n8k16.row.col.f32.bf16.bf16.f32 "
        "{%0,%1,%2,%3}, {%4,%5,%6,%7}, {%8,%9}, {%0,%1,%2,%3};"
        : "+f"(c[0]), "+f"(c[1]), "+f"(c[2]), "+f"(c[3])
        : "r"(a[0]), "r"(a[1]), "r"(a[2]), "r"(a[3]), "r"(b0), "r"(b1));
}

// ---------------- fp32 -> bf16 hi/lo split ----------------
__global__ void split_bf16_kernel(const float* __restrict__ src,
                                  __nv_bfloat16* __restrict__ hi,
                                  __nv_bfloat16* __restrict__ lo, int n4) {
    int i = blockIdx.x * blockDim.x + threadIdx.x;
    if (i >= n4) return;
    float4 v = ((const float4*)src)[i];
    __nv_bfloat16 h0 = __float2bfloat16(v.x);
    __nv_bfloat16 h1 = __float2bfloat16(v.y);
    __nv_bfloat16 h2 = __float2bfloat16(v.z);
    __nv_bfloat16 h3 = __float2bfloat16(v.w);
    __nv_bfloat16 l0 = __float2bfloat16(v.x - __bfloat162float(h0));
    __nv_bfloat16 l1 = __float2bfloat16(v.y - __bfloat162float(h1));
    __nv_bfloat16 l2 = __float2bfloat16(v.z - __bfloat162float(h2));
    __nv_bfloat16 l3 = __float2bfloat16(v.w - __bfloat162float(h3));
    ushort4 hv, lv;
    hv.x = __bfloat16_as_ushort(h0); hv.y = __bfloat16_as_ushort(h1);
    hv.z = __bfloat16_as_ushort(h2); hv.w = __bfloat16_as_ushort(h3);
    lv.x = __bfloat16_as_ushort(l0); lv.y = __bfloat16_as_ushort(l1);
    lv.z = __bfloat16_as_ushort(l2); lv.w = __bfloat16_as_ushort(l3);
    ((ushort4*)hi)[i] = hv;
    ((ushort4*)lo)[i] = lv;
}

// ---------------- RoPE table ----------------
__global__ void rope_table_kernel(float* ctab, float* stab) {
    int idx = blockIdx.x * blockDim.x + threadIdx.x;
    if (idx >= SEQ * 64) return;
    int pos = idx >> 6;
    int j   = idx & 63;
    float invf = expf(-(float)j * (9.210340371976184f / 64.0f));
    float arg = (float)pos * invf;
    float s, c;
    sincosf(arg, &s, &c);
    ctab[idx] = c;
    stab[idx] = s;
}

// ---------------- in-place RoPE on [B,S,nheads,128] ----------------
__global__ void rope_apply_kernel(float* __restrict__ t, const float* __restrict__ ctab,
                                  const float* __restrict__ stab, int nheads) {
    int idx = blockIdx.x * blockDim.x + threadIdx.x;
    int total = BATCH * SEQ * nheads * 64;
    if (idx >= total) return;
    int j  = idx & 63;
    int tt = idx >> 6;
    int h  = tt % nheads;
    int t2 = tt / nheads;
    int s  = t2 % SEQ;
    int b  = t2 / SEQ;
    float c  = ctab[s * 64 + j];
    float sn = stab[s * 64 + j];
    size_t base = (((size_t)b * SEQ + s) * nheads + h) * DHEAD;
    float x0 = t[base + j];
    float x1 = t[base + 64 + j];
    t[base + j]      = x0 * c - x1 * sn;
    t[base + 64 + j] = x1 * c + x0 * sn;
}

// ---------------- warp-MMA GEMM: C[M,N] = A[M,K] @ B[N,K]^T + bias ----------------
// A,B given as bf16 hi/lo pairs (3-pass: hh + hl + lh).
// 128x128 CTA tile, BK=32, 8 warps (32m x 64n each), cp.async double buffer.
// smem tile layout: rows with stride 40 bf16 (80B) -> conflict-free ldmatrix.
#define TSTRIDE 40
#define TILE_B  (128 * TSTRIDE * 2)      // 10240 bytes per tile
#define STAGE_B (4 * TILE_B)             // Ahi|Alo|Bhi|Blo = 40960
#define GEMM_SMEM (2 * STAGE_B)          // 81920

__global__ __launch_bounds__(256, 1)
void gemm_mma_bias(const __nv_bfloat16* __restrict__ Ahi, const __nv_bfloat16* __restrict__ Alo,
                   const __nv_bfloat16* __restrict__ Bhi, const __nv_bfloat16* __restrict__ Blo,
                   const float* __restrict__ bias, float* __restrict__ C,
                   int M, int N, int K) {
    extern __shared__ char dsm[];
    const uint32_t sbase = smem_u32(dsm);

    const int tid  = threadIdx.x;
    const int wid  = tid >> 5;
    const int lane = tid & 31;

    const int bm = blockIdx.y * 128;
    const int bn = blockIdx.x * 128;
    const int warp_m = (wid & 3) * 32;
    const int warp_n = (wid >> 2) * 64;

    const __nv_bfloat16* srcs[4] = {Ahi, Alo, Bhi, Blo};
    const int rowbase[4] = {bm, bm, bn, bn};

    // ldmatrix lane offsets
    const int a_r = lane & 15;
    const int a_k = (lane >> 4) * 8;
    const int b_r = ((lane >> 4) << 3) + (lane & 7);
    const int b_k = ((lane >> 3) & 1) * 8;

    float acc[2][8][4];
#pragma unroll
    for (int mi = 0; mi < 2; mi++)
#pragma unroll
        for (int ni = 0; ni < 8; ni++)
#pragma unroll
            for (int j = 0; j < 4; j++) acc[mi][ni][j] = 0.f;

    const int NC = K >> 5;   // chunks of 32

    // preload chunk 0 into stage 0 (full tile: 512 x 16B segments per tile)
#pragma unroll
    for (int t = 0; t < 4; t++) {
#pragma unroll
        for (int s = 0; s < 2; s++) {
            int seg = tid + s * 256;          // 0..511
            int row = seg >> 2;
            int qq  = seg & 3;
            const __nv_bfloat16* g = srcs[t] + (size_t)(rowbase[t] + row) * K + qq * 8;
            cp16(sbase + t * TILE_B + (uint32_t)(row * TSTRIDE + qq * 8) * 2, g);
        }
    }
    CP_COMMIT();

    for (int c = 0; c < NC; c++) {
        CP_WAIT0();
        __syncthreads();

        if (c + 1 < NC) {
            const uint32_t stg = sbase + ((c + 1) & 1) * STAGE_B;
            const int kt = (c + 1) << 5;
#pragma unroll
            for (int t = 0; t < 4; t++) {
#pragma unroll
                for (int s = 0; s < 2; s++) {
                    int seg = tid + s * 256;
                    int row = seg >> 2;
                    int qq  = seg & 3;
                    const __nv_bfloat16* g = srcs[t] + (size_t)(rowbase[t] + row) * K + kt + qq * 8;
                    cp16(stg + t * TILE_B + (uint32_t)(row * TSTRIDE + qq * 8) * 2, g);
                }
            }
            CP_COMMIT();
        }

        const uint32_t stage = sbase + (c & 1) * STAGE_B;
#pragma unroll
        for (int ka = 0; ka < 32; ka += 16) {
            uint32_t ah[2][4], al[2][4], bh[4][4], bl[4][4];
#pragma unroll
            for (int mi = 0; mi < 2; mi++) {
                uint32_t ro = (uint32_t)((warp_m + mi * 16 + a_r) * TSTRIDE + ka + a_k) * 2;
                ldm_x4(ah[mi], stage + 0 * TILE_B + ro);
                ldm_x4(al[mi], stage + 1 * TILE_B + ro);
            }
#pragma unroll
            for (int nj = 0; nj < 4; nj++) {
                uint32_t ro = (uint32_t)((warp_n + nj * 16 + b_r) * TSTRIDE + ka + b_k) * 2;
                ldm_x4(bh[nj], stage + 2 * TILE_B + ro);
                ldm_x4(bl[nj], stage + 3 * TILE_B + ro);
            }
#pragma unroll
            for (int mi = 0; mi < 2; mi++)
#pragma unroll
                for (int ni = 0; ni < 8; ni++) {
                    const int nj = ni >> 1;
                    const int s  = (ni & 1) * 2;
                    mma16816(acc[mi][ni], ah[mi], bh[nj][s], bh[nj][s + 1]);
                    mma16816(acc[mi][ni], ah[mi], bl[nj][s], bl[nj][s + 1]);
                    mma16816(acc[mi][ni], al[mi], bh[nj][s], bh[nj][s + 1]);
                }
        }
        __syncthreads();
    }

    // epilogue: write C + bias
    const int quad = lane >> 2;
    const int tcol = lane & 3;
#pragma unroll
    for (int mi = 0; mi < 2; mi++)
#pragma unroll
        for (int ni = 0; ni < 8; ni++) {
            const int m0 = bm + warp_m + mi * 16 + quad;
            const int n0 = bn + warp_n + ni * 8 + tcol * 2;
            const float b0 = bias[n0], b1 = bias[n0 + 1];
            float2 w0 = make_float2(acc[mi][ni][0] + b0, acc[mi][ni][1] + b1);
            float2 w1 = make_float2(acc[mi][ni][2] + b0, acc[mi][ni][3] + b1);
            *(float2*)&C[(size_t)m0 * N + n0]       = w0;
            *(float2*)&C[(size_t)(m0 + 8) * N + n0] = w1;
        }
}

// ---------------- flash attention (fp32, causal, GQA) ----------------
#define FL_SMEM_FLOATS (128*64 + 128*64 + 64*128 + 64*65 + 64 + 64 + 64 + 4*64 + 4*64)
#define FL_SMEM_BYTES  (FL_SMEM_FLOATS * 4)

__global__ __launch_bounds__(256)
void flash_attn_kernel(const float* __restrict__ Q, const float* __restrict__ K,
                       const float* __restrict__ V, float* __restrict__ O) {
    extern __shared__ float sm[];
    float* Qs   = sm;
    float* Ks   = Qs + 128 * 64;
    float* Vs   = Ks + 128 * 64;
    float* Ss   = Vs + 64 * 128;
    float* mrow = Ss + 64 * 65;
    float* lrow = mrow + 64;
    float* resc = lrow + 64;
    float* pmax = resc + 64;
    float* psum = pmax + 4 * 64;

    const int qt  = blockIdx.x;
    const int bh  = blockIdx.y;
    const int b   = bh >> 4;
    const int h   = bh & 15;
    const int kvh = h / GQA;
    const int q0  = qt * 64;
    const int tid = threadIdx.x;
    const float scale = 0.08838834764831845f;

#pragma unroll
    for (int it = 0; it < 8; it++) {
        int idx = tid + it * 256;
        int r   = idx >> 5;
        int d4  = (idx & 31) * 4;
        float4 v = *(const float4*)&Q[(((size_t)b * SEQ + q0 + r) * H_Q + h) * DHEAD + d4];
        Qs[(d4 + 0) * 64 + r] = v.x * scale;
        Qs[(d4 + 1) * 64 + r] = v.y * scale;
        Qs[(d4 + 2) * 64 + r] = v.z * scale;
        Qs[(d4 + 3) * 64 + r] = v.w * scale;
    }
    if (tid < 64) { mrow[tid] = -1e30f; lrow[tid] = 0.f; }

    float o[4][8];
#pragma unroll
    for (int i = 0; i < 4; i++)
#pragma unroll
        for (int j = 0; j < 8; j++) o[i][j] = 0.f;

    __syncthreads();

    for (int kt = 0; kt <= qt; kt++) {
        const int k0 = kt * 64;
#pragma unroll
        for (int it = 0; it < 8; it++) {
            int idx = tid + it * 256;
            int c   = idx >> 5;
            int d4  = (idx & 31) * 4;
            size_t gbase = (((size_t)b * SEQ + k0 + c) * H_KV + kvh) * DHEAD + d4;
            float4 kv = *(const float4*)&K[gbase];
            Ks[(d4 + 0) * 64 + c] = kv.x;
            Ks[(d4 + 1) * 64 + c] = kv.y;
            Ks[(d4 + 2) * 64 + c] = kv.z;
            Ks[(d4 + 3) * 64 + c] = kv.w;
            float4 vv = *(const float4*)&V[gbase];
            *(float4*)&Vs[c * 128 + d4] = vv;
        }
        __syncthreads();

        {
            const int tr = tid >> 4;
            const int tc = tid & 15;
            float s4[4][4];
#pragma unroll
            for (int i = 0; i < 4; i++)
#pragma unroll
                for (int j = 0; j < 4; j++) s4[i][j] = 0.f;

            for (int d = 0; d < 128; d++) {
                float4 qv = *(const float4*)&Qs[d * 64 + tr * 4];
                float4 kv = *(const float4*)&Ks[d * 64 + tc * 4];
                float qa[4] = {qv.x, qv.y, qv.z, qv.w};
                float ka[4] = {kv.x, kv.y, kv.z, kv.w};
#pragma unroll
                for (int i = 0; i < 4; i++)
#pragma unroll
                    for (int j = 0; j < 4; j++) s4[i][j] += qa[i] * ka[j];
            }
            if (kt == qt) {
#pragma unroll
                for (int i = 0; i < 4; i++)
#pragma unroll
                    for (int j = 0; j < 4; j++)
                        if (k0 + tc * 4 + j > q0 + tr * 4 + i) s4[i][j] = -1e30f;
            }
#pragma unroll
            for (int i = 0; i < 4; i++)
#pragma unroll
                for (int j = 0; j < 4; j++)
                    Ss[(tr * 4 + i) * 65 + tc * 4 + j] = s4[i][j];
        }
        __syncthreads();

        {
            int r = tid & 63, seg = tid >> 6;
            float lm = -1e30f;
#pragma unroll
            for (int c = 0; c < 16; c++) lm = fmaxf(lm, Ss[r * 65 + seg * 16 + c]);
            pmax[seg * 64 + r] = lm;
        }
        __syncthreads();
        if (tid < 64) {
            int r = tid;
            float mo = mrow[r];
            float mn = fmaxf(fmaxf(pmax[r], pmax[64 + r]), fmaxf(pmax[128 + r], pmax[192 + r]));
            mn = fmaxf(mo, mn);
            resc[r] = __expf(mo - mn);
            mrow[r] = mn;
        }
        __syncthreads();
        {
            int r = tid & 63, seg = tid >> 6;
            float mn = mrow[r];
            float sum = 0.f;
#pragma unroll
            for (int c = 0; c < 16; c++) {
                float p = __expf(Ss[r * 65 + seg * 16 + c] - mn);
                Ss[r * 65 + seg * 16 + c] = p;
                sum += p;
            }
            psum[seg * 64 + r] = sum;
        }
        __syncthreads();
        if (tid < 64) {
            int r = tid;
            lrow[r] = lrow[r] * resc[r] + psum[r] + psum[64 + r] + psum[128 + r] + psum[192 + r];
        }

        {
            const int rg = tid >> 4;
            const int cg = tid & 15;
            float rs[4];
#pragma unroll
            for (int i = 0; i < 4; i++) rs[i] = resc[rg * 4 + i];
#pragma unroll
            for (int i = 0; i < 4; i++)
#pragma unroll
                for (int j = 0; j < 8; j++) o[i][j] *= rs[i];

            for (int kk = 0; kk < 64; kk++) {
                float pr[4];
#pragma unroll
                for (int i = 0; i < 4; i++) pr[i] = Ss[(rg * 4 + i) * 65 + kk];
                float4 v0 = *(const float4*)&Vs[kk * 128 + cg * 8];
                float4 v1 = *(const float4*)&Vs[kk * 128 + cg * 8 + 4];
                float va[8] = {v0.x, v0.y, v0.z, v0.w, v1.x, v1.y, v1.z, v1.w};
#pragma unroll
                for (int i = 0; i < 4; i++)
#pragma unroll
                    for (int j = 0; j < 8; j++) o[i][j] += pr[i] * va[j];
            }
        }
        __syncthreads();
    }

    {
        const int rg = tid >> 4;
        const int cg = tid & 15;
#pragma unroll
        for (int i = 0; i < 4; i++) {
            float inv = 1.f / lrow[rg * 4 + i];
            float* op = &O[(((size_t)b * SEQ + q0 + rg * 4 + i) * H_Q + h) * DHEAD + cg * 8];
            float4 w0, w1;
            w0.x = o[i][0] * inv; w0.y = o[i][1] * inv;
            w0.z = o[i][2] * inv; w0.w = o[i][3] * inv;
            w1.x = o[i][4] * inv; w1.y = o[i][5] * inv;
            w1.z = o[i][6] * inv; w1.w = o[i][7] * inv;
            *(float4*)&op[0] = w0;
            *(float4*)&op[4] = w1;
        }
    }
}

// ---------------- launch ----------------
extern "C" void kernel_launch(void* const* d_in, const int* in_sizes, int n_in,
                              void* d_out, int out_size) {
    const float* x  = (const float*)d_in[0];
    const float* wq = (const float*)d_in[1];
    const float* bq = (const float*)d_in[2];
    const float* wk = (const float*)d_in[3];
    const float* bk = (const float*)d_in[4];
    const float* wv = (const float*)d_in[5];
    const float* bv = (const float*)d_in[6];
    const float* wo = (const float*)d_in[7];
    const float* bo = (const float*)d_in[8];
    float* out = (float*)d_out;

    float *q, *k, *v, *o, *ctab, *stab;
    cudaGetSymbolAddress((void**)&q, g_q);
    cudaGetSymbolAddress((void**)&k, g_k);
    cudaGetSymbolAddress((void**)&v, g_v);
    cudaGetSymbolAddress((void**)&o, g_o);
    cudaGetSymbolAddress((void**)&ctab, g_cos);
    cudaGetSymbolAddress((void**)&stab, g_sin);

    __nv_bfloat16 *xhi, *xlo, *wqhi, *wqlo, *wkhi, *wklo, *wvhi, *wvlo, *wohi, *wolo, *ohi, *olo;
    cudaGetSymbolAddress((void**)&xhi, g_xhi);   cudaGetSymbolAddress((void**)&xlo, g_xlo);
    cudaGetSymbolAddress((void**)&wqhi, g_wqhi); cudaGetSymbolAddress((void**)&wqlo, g_wqlo);
    cudaGetSymbolAddress((void**)&wkhi, g_wkhi); cudaGetSymbolAddress((void**)&wklo, g_wklo);
    cudaGetSymbolAddress((void**)&wvhi, g_wvhi); cudaGetSymbolAddress((void**)&wvlo, g_wvlo);
    cudaGetSymbolAddress((void**)&wohi, g_wohi); cudaGetSymbolAddress((void**)&wolo, g_wolo);
    cudaGetSymbolAddress((void**)&ohi, g_ohi);   cudaGetSymbolAddress((void**)&olo, g_olo);

    const int M = BATCH * SEQ;   // 8192

    // RoPE tables
    rope_table_kernel<<<(SEQ * 64 + 255) / 256, 256>>>(ctab, stab);

    // fp32 -> bf16 hi/lo splits
    split_bf16_kernel<<<(XN / 4 + 255) / 256, 256>>>(x,  xhi,  xlo,  XN / 4);
    split_bf16_kernel<<<(WQN / 4 + 255) / 256, 256>>>(wq, wqhi, wqlo, WQN / 4);
    split_bf16_kernel<<<(WKN / 4 + 255) / 256, 256>>>(wk, wkhi, wklo, WKN / 4);
    split_bf16_kernel<<<(WKN / 4 + 255) / 256, 256>>>(wv, wvhi, wvlo, WKN / 4);
    split_bf16_kernel<<<(WQN / 4 + 255) / 256, 256>>>(wo, wohi, wolo, WQN / 4);

    cudaFuncSetAttribute(gemm_mma_bias, cudaFuncAttributeMaxDynamicSharedMemorySize, GEMM_SMEM);

    // QKV projections (warp MMA, bf16 3-pass)
    gemm_mma_bias<<<dim3(EMB / 128, M / 128), 256, GEMM_SMEM>>>(xhi, xlo, wqhi, wqlo, bq, q, M, EMB, EMB);
    gemm_mma_bias<<<dim3(KVDIM / 128, M / 128), 256, GEMM_SMEM>>>(xhi, xlo, wkhi, wklo, bk, k, M, KVDIM, EMB);
    gemm_mma_bias<<<dim3(KVDIM / 128, M / 128), 256, GEMM_SMEM>>>(xhi, xlo, wvhi, wvlo, bv, v, M, KVDIM, EMB);

    // RoPE on q and k (in place)
    {
        int tq = BATCH * SEQ * H_Q * 64;
        rope_apply_kernel<<<(tq + 255) / 256, 256>>>(q, ctab, stab, H_Q);
        int tk = BATCH * SEQ * H_KV * 64;
        rope_apply_kernel<<<(tk + 255) / 256, 256>>>(k, ctab, stab, H_KV);
    }

    // flash attention (fp32)
    cudaFuncSetAttribute(flash_attn_kernel, cudaFuncAttributeMaxDynamicSharedMemorySize,
                         FL_SMEM_BYTES);
    flash_attn_kernel<<<dim3(SEQ / 64, BATCH * H_Q), 256, FL_SMEM_BYTES>>>(q, k, v, o);

    // output projection (warp MMA)
    split_bf16_kernel<<<(XN / 4 + 255) / 256, 256>>>(o, ohi, olo, XN / 4);
    gemm_mma_bias<<<dim3(EMB / 128, M / 128), 256, GEMM_SMEM>>>(ohi, olo, wohi, wolo, bo, out, M, EMB, EMB);
}

// round 5
// speedup vs baseline: 3.2296x; 2.2091x over previous
#include <cuda_runtime.h>
#include <cuda_bf16.h>
#include <math.h>
#include <stdint.h>

#define BATCH 4
#define SEQ   2048
#define EMB   2048
#define H_Q   16
#define H_KV  4
#define DHEAD 128
#define KVDIM (H_KV*DHEAD)     // 512
#define GQA   (H_Q/H_KV)       // 4

// ---------------- scratch (no allocations allowed) ----------------
__device__ float g_q[BATCH*SEQ*EMB];     // [B,S,H,D] fp32 (pre-rope)
__device__ float g_k[BATCH*SEQ*KVDIM];   // [B,S,KV,D]
__device__ float g_v[BATCH*SEQ*KVDIM];
__device__ float g_o[BATCH*SEQ*EMB];     // attention out fp32
__device__ float g_cos[SEQ*64];
__device__ float g_sin[SEQ*64];

#define XN   (BATCH*SEQ*EMB)       // 16M
#define KN   (BATCH*SEQ*KVDIM)     // 4M
#define WQN  (EMB*EMB)
#define WKN  (KVDIM*EMB)
__device__ __nv_bfloat16 g_xhi[XN],  g_xlo[XN];
__device__ __nv_bfloat16 g_wqhi[WQN], g_wqlo[WQN];
__device__ __nv_bfloat16 g_wkhi[WKN], g_wklo[WKN];
__device__ __nv_bfloat16 g_wvhi[WKN], g_wvlo[WKN];
__device__ __nv_bfloat16 g_wohi[WQN], g_wolo[WQN];
__device__ __nv_bfloat16 g_ohi[XN],  g_olo[XN];
// flash inputs (post-rope, scaled)
__device__ __nv_bfloat16 g_qhi[XN], g_qlo[XN];
__device__ __nv_bfloat16 g_khi[KN], g_klo[KN];
__device__ __nv_bfloat16 g_vhi[KN], g_vlo[KN];

// ---------------- helpers ----------------
__device__ __forceinline__ uint32_t smem_u32(const void* p) {
    uint32_t a;
    asm("{ .reg .u64 t; cvta.to.shared.u64 t, %1; cvt.u32.u64 %0, t; }" : "=r"(a) : "l"(p));
    return a;
}
__device__ __forceinline__ void cp16(uint32_t dst, const void* src) {
    asm volatile("cp.async.cg.shared.global [%0], [%1], 16;" :: "r"(dst), "l"(src) : "memory");
}
#define CP_COMMIT() asm volatile("cp.async.commit_group;" ::: "memory")
#define CP_WAIT0()  asm volatile("cp.async.wait_group 0;" ::: "memory")

__device__ __forceinline__ void ldm_x4(uint32_t* r, uint32_t addr) {
    asm volatile("ldmatrix.sync.aligned.m8n8.x4.shared.b16 {%0,%1,%2,%3}, [%4];"
                 : "=r"(r[0]), "=r"(r[1]), "=r"(r[2]), "=r"(r[3]) : "r"(addr));
}
__device__ __forceinline__ void ldm_x4_t(uint32_t* r, uint32_t addr) {
    asm volatile("ldmatrix.sync.aligned.m8n8.x4.trans.shared.b16 {%0,%1,%2,%3}, [%4];"
                 : "=r"(r[0]), "=r"(r[1]), "=r"(r[2]), "=r"(r[3]) : "r"(addr));
}
__device__ __forceinline__ void mma16816(float* c, const uint32_t* a, uint32_t b0, uint32_t b1) {
    asm volatile(
        "mma.sync.aligned.m16n8k16.row.col.f32.bf16.bf16.f32 "
        "{%0,%1,%2,%3}, {%4,%5,%6,%7}, {%8,%9}, {%0,%1,%2,%3};"
        : "+f"(c[0]), "+f"(c[1]), "+f"(c[2]), "+f"(c[3])
        : "r"(a[0]), "r"(a[1]), "r"(a[2]), "r"(a[3]), "r"(b0), "r"(b1));
}
__device__ __forceinline__ uint32_t packbf(float lo, float hi) {
    uint32_t r;
    asm("cvt.rn.bf16x2.f32 %0, %1, %2;" : "=r"(r) : "f"(hi), "f"(lo));
    return r;
}
__device__ __forceinline__ float bfround(float x) {
    return __bfloat162float(__float2bfloat16(x));
}

// ---------------- fp32 -> bf16 hi/lo split ----------------
__global__ void split_bf16_kernel(const float* __restrict__ src,
                                  __nv_bfloat16* __restrict__ hi,
                                  __nv_bfloat16* __restrict__ lo, int n4) {
    int i = blockIdx.x * blockDim.x + threadIdx.x;
    if (i >= n4) return;
    float4 v = ((const float4*)src)[i];
    __nv_bfloat16 h0 = __float2bfloat16(v.x);
    __nv_bfloat16 h1 = __float2bfloat16(v.y);
    __nv_bfloat16 h2 = __float2bfloat16(v.z);
    __nv_bfloat16 h3 = __float2bfloat16(v.w);
    __nv_bfloat16 l0 = __float2bfloat16(v.x - __bfloat162float(h0));
    __nv_bfloat16 l1 = __float2bfloat16(v.y - __bfloat162float(h1));
    __nv_bfloat16 l2 = __float2bfloat16(v.z - __bfloat162float(h2));
    __nv_bfloat16 l3 = __float2bfloat16(v.w - __bfloat162float(h3));
    ushort4 hv, lv;
    hv.x = __bfloat16_as_ushort(h0); hv.y = __bfloat16_as_ushort(h1);
    hv.z = __bfloat16_as_ushort(h2); hv.w = __bfloat16_as_ushort(h3);
    lv.x = __bfloat16_as_ushort(l0); lv.y = __bfloat16_as_ushort(l1);
    lv.z = __bfloat16_as_ushort(l2); lv.w = __bfloat16_as_ushort(l3);
    ((ushort4*)hi)[i] = hv;
    ((ushort4*)lo)[i] = lv;
}

// ---------------- RoPE table ----------------
__global__ void rope_table_kernel(float* ctab, float* stab) {
    int idx = blockIdx.x * blockDim.x + threadIdx.x;
    if (idx >= SEQ * 64) return;
    int pos = idx >> 6;
    int j   = idx & 63;
    float invf = expf(-(float)j * (9.210340371976184f / 64.0f));
    float arg = (float)pos * invf;
    float s, c;
    sincosf(arg, &s, &c);
    ctab[idx] = c;
    stab[idx] = s;
}

// ---------------- RoPE + scale + hi/lo split: fp32 [B,S,nh,128] -> bf16 pair ----------------
__global__ void rope_split_kernel(const float* __restrict__ src,
                                  const float* __restrict__ ctab, const float* __restrict__ stab,
                                  __nv_bfloat16* __restrict__ hi, __nv_bfloat16* __restrict__ lo,
                                  int nheads, float scale) {
    int idx = blockIdx.x * blockDim.x + threadIdx.x;
    int total = BATCH * SEQ * nheads * 64;
    if (idx >= total) return;
    int j  = idx & 63;
    int tt = idx >> 6;
    int h  = tt % nheads;
    int t2 = tt / nheads;
    int s  = t2 % SEQ;
    int b  = t2 / SEQ;
    float c  = ctab[s * 64 + j];
    float sn = stab[s * 64 + j];
    size_t base = (((size_t)b * SEQ + s) * nheads + h) * DHEAD;
    float x0 = src[base + j];
    float x1 = src[base + 64 + j];
    float y0 = (x0 * c - x1 * sn) * scale;
    float y1 = (x1 * c + x0 * sn) * scale;
    float h0 = bfround(y0), h1 = bfround(y1);
    hi[base + j]      = __float2bfloat16(y0);
    hi[base + 64 + j] = __float2bfloat16(y1);
    lo[base + j]      = __float2bfloat16(y0 - h0);
    lo[base + 64 + j] = __float2bfloat16(y1 - h1);
}

// ---------------- warp-MMA GEMM (unchanged from R4) ----------------
#define TSTRIDE 40
#define TILE_B  (128 * TSTRIDE * 2)
#define STAGE_B (4 * TILE_B)
#define GEMM_SMEM (2 * STAGE_B)

__global__ __launch_bounds__(256, 1)
void gemm_mma_bias(const __nv_bfloat16* __restrict__ Ahi, const __nv_bfloat16* __restrict__ Alo,
                   const __nv_bfloat16* __restrict__ Bhi, const __nv_bfloat16* __restrict__ Blo,
                   const float* __restrict__ bias, float* __restrict__ C,
                   int M, int N, int K) {
    extern __shared__ char dsm[];
    const uint32_t sbase = smem_u32(dsm);

    const int tid  = threadIdx.x;
    const int wid  = tid >> 5;
    const int lane = tid & 31;

    const int bm = blockIdx.y * 128;
    const int bn = blockIdx.x * 128;
    const int warp_m = (wid & 3) * 32;
    const int warp_n = (wid >> 2) * 64;

    const __nv_bfloat16* srcs[4] = {Ahi, Alo, Bhi, Blo};
    const int rowbase[4] = {bm, bm, bn, bn};

    const int a_r = lane & 15;
    const int a_k = (lane >> 4) * 8;
    const int b_r = ((lane >> 4) << 3) + (lane & 7);
    const int b_k = ((lane >> 3) & 1) * 8;

    float acc[2][8][4];
#pragma unroll
    for (int mi = 0; mi < 2; mi++)
#pragma unroll
        for (int ni = 0; ni < 8; ni++)
#pragma unroll
            for (int j = 0; j < 4; j++) acc[mi][ni][j] = 0.f;

    const int NC = K >> 5;

#pragma unroll
    for (int t = 0; t < 4; t++) {
#pragma unroll
        for (int s = 0; s < 2; s++) {
            int seg = tid + s * 256;
            int row = seg >> 2;
            int qq  = seg & 3;
            const __nv_bfloat16* g = srcs[t] + (size_t)(rowbase[t] + row) * K + qq * 8;
            cp16(sbase + t * TILE_B + (uint32_t)(row * TSTRIDE + qq * 8) * 2, g);
        }
    }
    CP_COMMIT();

    for (int c = 0; c < NC; c++) {
        CP_WAIT0();
        __syncthreads();

        if (c + 1 < NC) {
            const uint32_t stg = sbase + ((c + 1) & 1) * STAGE_B;
            const int kt = (c + 1) << 5;
#pragma unroll
            for (int t = 0; t < 4; t++) {
#pragma unroll
                for (int s = 0; s < 2; s++) {
                    int seg = tid + s * 256;
                    int row = seg >> 2;
                    int qq  = seg & 3;
                    const __nv_bfloat16* g = srcs[t] + (size_t)(rowbase[t] + row) * K + kt + qq * 8;
                    cp16(stg + t * TILE_B + (uint32_t)(row * TSTRIDE + qq * 8) * 2, g);
                }
            }
            CP_COMMIT();
        }

        const uint32_t stage = sbase + (c & 1) * STAGE_B;
#pragma unroll
        for (int ka = 0; ka < 32; ka += 16) {
            uint32_t ah[2][4], al[2][4], bh[4][4], bl[4][4];
#pragma unroll
            for (int mi = 0; mi < 2; mi++) {
                uint32_t ro = (uint32_t)((warp_m + mi * 16 + a_r) * TSTRIDE + ka + a_k) * 2;
                ldm_x4(ah[mi], stage + 0 * TILE_B + ro);
                ldm_x4(al[mi], stage + 1 * TILE_B + ro);
            }
#pragma unroll
            for (int nj = 0; nj < 4; nj++) {
                uint32_t ro = (uint32_t)((warp_n + nj * 16 + b_r) * TSTRIDE + ka + b_k) * 2;
                ldm_x4(bh[nj], stage + 2 * TILE_B + ro);
                ldm_x4(bl[nj], stage + 3 * TILE_B + ro);
            }
#pragma unroll
            for (int mi = 0; mi < 2; mi++)
#pragma unroll
                for (int ni = 0; ni < 8; ni++) {
                    const int nj = ni >> 1;
                    const int s  = (ni & 1) * 2;
                    mma16816(acc[mi][ni], ah[mi], bh[nj][s], bh[nj][s + 1]);
                    mma16816(acc[mi][ni], ah[mi], bl[nj][s], bl[nj][s + 1]);
                    mma16816(acc[mi][ni], al[mi], bh[nj][s], bh[nj][s + 1]);
                }
        }
        __syncthreads();
    }

    const int quad = lane >> 2;
    const int tcol = lane & 3;
#pragma unroll
    for (int mi = 0; mi < 2; mi++)
#pragma unroll
        for (int ni = 0; ni < 8; ni++) {
            const int m0 = bm + warp_m + mi * 16 + quad;
            const int n0 = bn + warp_n + ni * 8 + tcol * 2;
            const float b0 = bias[n0], b1 = bias[n0 + 1];
            float2 w0 = make_float2(acc[mi][ni][0] + b0, acc[mi][ni][1] + b1);
            float2 w1 = make_float2(acc[mi][ni][2] + b0, acc[mi][ni][3] + b1);
            *(float2*)&C[(size_t)m0 * N + n0]       = w0;
            *(float2*)&C[(size_t)(m0 + 8) * N + n0] = w1;
        }
}

// ---------------- tensor-core flash attention ----------------
// CTA: 128 threads (4 warps), q-tile 64 (16 rows/warp), k-tile 64, D=128.
// smem: Vhi | Vlo | Khi | Klo, each 64 x 136 bf16 (17408 B). Q staged in V region.
#define KSTR 136
#define FL2_TILE (64 * KSTR * 2)     // 17408
#define FL2_SMEM (4 * FL2_TILE)      // 69632

__global__ __launch_bounds__(128)
void flash_mma_kernel(const __nv_bfloat16* __restrict__ Qhi, const __nv_bfloat16* __restrict__ Qlo,
                      const __nv_bfloat16* __restrict__ Khi, const __nv_bfloat16* __restrict__ Klo,
                      const __nv_bfloat16* __restrict__ Vhi, const __nv_bfloat16* __restrict__ Vlo,
                      float* __restrict__ O) {
    extern __shared__ char sm2[];
    const uint32_t sb = smem_u32(sm2);

    const int qt  = gridDim.x - 1 - blockIdx.x;   // heavy tiles first
    const int bh  = blockIdx.y;
    const int b   = bh >> 4;
    const int h   = bh & 15;
    const int kvh = h >> 2;
    const int q0  = qt * 64;
    const int tid = threadIdx.x;
    const int wid = tid >> 5;
    const int lane = tid & 31;
    const int quad = lane >> 2;
    const int tcol = lane & 3;

    // ---- stage Q (hi/lo) into smem, load A-fragments, release smem ----
#pragma unroll
    for (int s = 0; s < 8; s++) {
        int seg = tid + s * 128;           // 0..1023
        int r   = seg >> 4;
        int cg  = seg & 15;
        size_t gofs = (((size_t)b * SEQ + q0 + r) * H_Q + h) * DHEAD + cg * 8;
        uint32_t so = (uint32_t)(r * KSTR + cg * 8) * 2;
        cp16(sb + so, Qhi + gofs);
        cp16(sb + FL2_TILE + so, Qlo + gofs);
    }
    CP_COMMIT();
    CP_WAIT0();
    __syncthreads();

    uint32_t qh[8][4], ql[8][4];
    {
        const int a_r = lane & 15;
        const int a_k = (lane >> 4) * 8;
#pragma unroll
        for (int ka = 0; ka < 8; ka++) {
            uint32_t ro = (uint32_t)((wid * 16 + a_r) * KSTR + ka * 16 + a_k) * 2;
            ldm_x4(qh[ka], sb + ro);
            ldm_x4(ql[ka], sb + FL2_TILE + ro);
        }
    }
    __syncthreads();

    float o_acc[16][4];
#pragma unroll
    for (int g = 0; g < 16; g++)
#pragma unroll
        for (int j = 0; j < 4; j++) o_acc[g][j] = 0.f;

    float m0 = -1e30f, m1 = -1e30f, l0 = 0.f, l1 = 0.f;

    const int b_r = ((lane >> 4) << 3) + (lane & 7);
    const int b_k = ((lane >> 3) & 1) * 8;
    // V trans-ldmatrix lane offsets
    const int v_kk = (lane & 7) + ((lane >> 3) & 1) * 8;
    const int v_d  = ((lane >> 4) & 1) * 8;

    for (int kt = 0; kt <= qt; kt++) {
        const int k0 = kt * 64;
        // load V(hi/lo) and K(hi/lo) tiles
#pragma unroll
        for (int s = 0; s < 8; s++) {
            int seg = tid + s * 128;
            int r   = seg >> 4;
            int cg  = seg & 15;
            size_t gofs = (((size_t)b * SEQ + k0 + r) * H_KV + kvh) * DHEAD + cg * 8;
            uint32_t so = (uint32_t)(r * KSTR + cg * 8) * 2;
            cp16(sb + 0 * FL2_TILE + so, Vhi + gofs);
            cp16(sb + 1 * FL2_TILE + so, Vlo + gofs);
            cp16(sb + 2 * FL2_TILE + so, Khi + gofs);
            cp16(sb + 3 * FL2_TILE + so, Klo + gofs);
        }
        CP_COMMIT();
        CP_WAIT0();
        __syncthreads();

        // ---- scores = Q K^T (3-pass) ----
        float sc[8][4];
#pragma unroll
        for (int ni = 0; ni < 8; ni++)
#pragma unroll
            for (int j = 0; j < 4; j++) sc[ni][j] = 0.f;

#pragma unroll
        for (int ka = 0; ka < 8; ka++) {
#pragma unroll
            for (int nj = 0; nj < 4; nj++) {
                uint32_t ro = (uint32_t)((nj * 16 + b_r) * KSTR + ka * 16 + b_k) * 2;
                uint32_t kh[4], kl[4];
                ldm_x4(kh, sb + 2 * FL2_TILE + ro);
                ldm_x4(kl, sb + 3 * FL2_TILE + ro);
#pragma unroll
                for (int half = 0; half < 2; half++) {
                    const int ni = nj * 2 + half;
                    const int s2 = half * 2;
                    mma16816(sc[ni], qh[ka], kh[s2], kh[s2 + 1]);
                    mma16816(sc[ni], qh[ka], kl[s2], kl[s2 + 1]);
                    mma16816(sc[ni], ql[ka], kh[s2], kh[s2 + 1]);
                }
            }
        }

        // ---- causal mask on diagonal tile ----
        if (kt == qt) {
            const int row0 = wid * 16 + quad;
#pragma unroll
            for (int ni = 0; ni < 8; ni++) {
                const int c0 = ni * 8 + 2 * tcol;
                if (c0 > row0)     sc[ni][0] = -1e30f;
                if (c0 + 1 > row0) sc[ni][1] = -1e30f;
                if (c0 > row0 + 8)     sc[ni][2] = -1e30f;
                if (c0 + 1 > row0 + 8) sc[ni][3] = -1e30f;
            }
        }

        // ---- online softmax (rows quad / quad+8) ----
        float mx0 = -1e30f, mx1 = -1e30f;
#pragma unroll
        for (int ni = 0; ni < 8; ni++) {
            mx0 = fmaxf(mx0, fmaxf(sc[ni][0], sc[ni][1]));
            mx1 = fmaxf(mx1, fmaxf(sc[ni][2], sc[ni][3]));
        }
        mx0 = fmaxf(mx0, __shfl_xor_sync(0xffffffffu, mx0, 1));
        mx0 = fmaxf(mx0, __shfl_xor_sync(0xffffffffu, mx0, 2));
        mx1 = fmaxf(mx1, __shfl_xor_sync(0xffffffffu, mx1, 1));
        mx1 = fmaxf(mx1, __shfl_xor_sync(0xffffffffu, mx1, 2));

        const float nm0 = fmaxf(m0, mx0);
        const float nm1 = fmaxf(m1, mx1);
        const float rs0 = __expf(m0 - nm0);
        const float rs1 = __expf(m1 - nm1);
        m0 = nm0; m1 = nm1;

        float ps0 = 0.f, ps1 = 0.f;
#pragma unroll
        for (int ni = 0; ni < 8; ni++) {
            sc[ni][0] = __expf(sc[ni][0] - nm0);
            sc[ni][1] = __expf(sc[ni][1] - nm0);
            sc[ni][2] = __expf(sc[ni][2] - nm1);
            sc[ni][3] = __expf(sc[ni][3] - nm1);
            ps0 += sc[ni][0] + sc[ni][1];
            ps1 += sc[ni][2] + sc[ni][3];
        }
        ps0 += __shfl_xor_sync(0xffffffffu, ps0, 1);
        ps0 += __shfl_xor_sync(0xffffffffu, ps0, 2);
        ps1 += __shfl_xor_sync(0xffffffffu, ps1, 1);
        ps1 += __shfl_xor_sync(0xffffffffu, ps1, 2);
        l0 = l0 * rs0 + ps0;
        l1 = l1 * rs1 + ps1;

#pragma unroll
        for (int g = 0; g < 16; g++) {
            o_acc[g][0] *= rs0; o_acc[g][1] *= rs0;
            o_acc[g][2] *= rs1; o_acc[g][3] *= rs1;
        }

        // ---- O += P V (3-pass, P repacked in-register) ----
#pragma unroll
        for (int t = 0; t < 4; t++) {
            float p00 = sc[2*t][0],   p01 = sc[2*t][1],   p02 = sc[2*t][2],   p03 = sc[2*t][3];
            float p10 = sc[2*t+1][0], p11 = sc[2*t+1][1], p12 = sc[2*t+1][2], p13 = sc[2*t+1][3];
            uint32_t aph[4], apl[4];
            aph[0] = packbf(p00, p01);
            aph[1] = packbf(p02, p03);
            aph[2] = packbf(p10, p11);
            aph[3] = packbf(p12, p13);
            apl[0] = packbf(p00 - bfround(p00), p01 - bfround(p01));
            apl[1] = packbf(p02 - bfround(p02), p03 - bfround(p03));
            apl[2] = packbf(p10 - bfround(p10), p11 - bfround(p11));
            apl[3] = packbf(p12 - bfround(p12), p13 - bfround(p13));

            const uint32_t vbase = sb + (uint32_t)((t * 16 + v_kk) * KSTR + v_d) * 2;
#pragma unroll
            for (int g = 0; g < 8; g++) {
                uint32_t vh[4], vl[4];
                ldm_x4_t(vh, vbase + (uint32_t)(g * 16) * 2);
                ldm_x4_t(vl, vbase + FL2_TILE + (uint32_t)(g * 16) * 2);
                mma16816(o_acc[g*2],   aph, vh[0], vh[1]);
                mma16816(o_acc[g*2+1], aph, vh[2], vh[3]);
                mma16816(o_acc[g*2],   aph, vl[0], vl[1]);
                mma16816(o_acc[g*2+1], aph, vl[2], vl[3]);
                mma16816(o_acc[g*2],   apl, vh[0], vh[1]);
                mma16816(o_acc[g*2+1], apl, vh[2], vh[3]);
            }
        }
        __syncthreads();
    }

    // ---- epilogue: normalize + store fp32 [B,S,H,D] ----
    const float inv0 = 1.f / l0;
    const float inv1 = 1.f / l1;
    const int row0 = q0 + wid * 16 + quad;
#pragma unroll
    for (int g = 0; g < 16; g++) {
        const int d = g * 8 + 2 * tcol;
        float2 w0 = make_float2(o_acc[g][0] * inv0, o_acc[g][1] * inv0);
        float2 w1 = make_float2(o_acc[g][2] * inv1, o_acc[g][3] * inv1);
        *(float2*)&O[(((size_t)b * SEQ + row0) * H_Q + h) * DHEAD + d]     = w0;
        *(float2*)&O[(((size_t)b * SEQ + row0 + 8) * H_Q + h) * DHEAD + d] = w1;
    }
}

// ---------------- launch ----------------
extern "C" void kernel_launch(void* const* d_in, const int* in_sizes, int n_in,
                              void* d_out, int out_size) {
    const float* x  = (const float*)d_in[0];
    const float* wq = (const float*)d_in[1];
    const float* bq = (const float*)d_in[2];
    const float* wk = (const float*)d_in[3];
    const float* bk = (const float*)d_in[4];
    const float* wv = (const float*)d_in[5];
    const float* bv = (const float*)d_in[6];
    const float* wo = (const float*)d_in[7];
    const float* bo = (const float*)d_in[8];
    float* out = (float*)d_out;

    float *q, *k, *v, *o, *ctab, *stab;
    cudaGetSymbolAddress((void**)&q, g_q);
    cudaGetSymbolAddress((void**)&k, g_k);
    cudaGetSymbolAddress((void**)&v, g_v);
    cudaGetSymbolAddress((void**)&o, g_o);
    cudaGetSymbolAddress((void**)&ctab, g_cos);
    cudaGetSymbolAddress((void**)&stab, g_sin);

    __nv_bfloat16 *xhi, *xlo, *wqhi, *wqlo, *wkhi, *wklo, *wvhi, *wvlo, *wohi, *wolo, *ohi, *olo;
    __nv_bfloat16 *qhi, *qlo, *khi, *klo, *vhi, *vlo;
    cudaGetSymbolAddress((void**)&xhi, g_xhi);   cudaGetSymbolAddress((void**)&xlo, g_xlo);
    cudaGetSymbolAddress((void**)&wqhi, g_wqhi); cudaGetSymbolAddress((void**)&wqlo, g_wqlo);
    cudaGetSymbolAddress((void**)&wkhi, g_wkhi); cudaGetSymbolAddress((void**)&wklo, g_wklo);
    cudaGetSymbolAddress((void**)&wvhi, g_wvhi); cudaGetSymbolAddress((void**)&wvlo, g_wvlo);
    cudaGetSymbolAddress((void**)&wohi, g_wohi); cudaGetSymbolAddress((void**)&wolo, g_wolo);
    cudaGetSymbolAddress((void**)&ohi, g_ohi);   cudaGetSymbolAddress((void**)&olo, g_olo);
    cudaGetSymbolAddress((void**)&qhi, g_qhi);   cudaGetSymbolAddress((void**)&qlo, g_qlo);
    cudaGetSymbolAddress((void**)&khi, g_khi);   cudaGetSymbolAddress((void**)&klo, g_klo);
    cudaGetSymbolAddress((void**)&vhi, g_vhi);   cudaGetSymbolAddress((void**)&vlo, g_vlo);

    const int M = BATCH * SEQ;   // 8192

    rope_table_kernel<<<(SEQ * 64 + 255) / 256, 256>>>(ctab, stab);

    split_bf16_kernel<<<(XN / 4 + 255) / 256, 256>>>(x,  xhi,  xlo,  XN / 4);
    split_bf16_kernel<<<(WQN / 4 + 255) / 256, 256>>>(wq, wqhi, wqlo, WQN / 4);
    split_bf16_kernel<<<(WKN / 4 + 255) / 256, 256>>>(wk, wkhi, wklo, WKN / 4);
    split_bf16_kernel<<<(WKN / 4 + 255) / 256, 256>>>(wv, wvhi, wvlo, WKN / 4);
    split_bf16_kernel<<<(WQN / 4 + 255) / 256, 256>>>(wo, wohi, wolo, WQN / 4);

    cudaFuncSetAttribute(gemm_mma_bias, cudaFuncAttributeMaxDynamicSharedMemorySize, GEMM_SMEM);

    gemm_mma_bias<<<dim3(EMB / 128, M / 128), 256, GEMM_SMEM>>>(xhi, xlo, wqhi, wqlo, bq, q, M, EMB, EMB);
    gemm_mma_bias<<<dim3(KVDIM / 128, M / 128), 256, GEMM_SMEM>>>(xhi, xlo, wkhi, wklo, bk, k, M, KVDIM, EMB);
    gemm_mma_bias<<<dim3(KVDIM / 128, M / 128), 256, GEMM_SMEM>>>(xhi, xlo, wvhi, wvlo, bv, v, M, KVDIM, EMB);

    // RoPE + scale + split -> flash inputs
    {
        const float qscale = 0.08838834764831845f;   // 1/sqrt(128)
        int tq = BATCH * SEQ * H_Q * 64;
        rope_split_kernel<<<(tq + 255) / 256, 256>>>(q, ctab, stab, qhi, qlo, H_Q, qscale);
        int tk = BATCH * SEQ * H_KV * 64;
        rope_split_kernel<<<(tk + 255) / 256, 256>>>(k, ctab, stab, khi, klo, H_KV, 1.0f);
        split_bf16_kernel<<<(KN / 4 + 255) / 256, 256>>>(v, vhi, vlo, KN / 4);
    }

    // tensor-core flash attention
    cudaFuncSetAttribute(flash_mma_kernel, cudaFuncAttributeMaxDynamicSharedMemorySize, FL2_SMEM);
    flash_mma_kernel<<<dim3(SEQ / 64, BATCH * H_Q), 128, FL2_SMEM>>>(qhi, qlo, khi, klo, vhi, vlo, o);

    // output projection
    split_bf16_kernel<<<(XN / 4 + 255) / 256, 256>>>(o, ohi, olo, XN / 4);
    gemm_mma_bias<<<dim3(EMB / 128, M / 128), 256, GEMM_SMEM>>>(ohi, olo, wohi, wolo, bo, out, M, EMB, EMB);
}